// round 16
// baseline (speedup 1.0000x reference)
#include <cuda_runtime.h>
#include <cuda_fp16.h>
#include <cstdint>

#define N_SRC 50000
#define N_DST 50000
#define NEDGE 800000
#define IN_DIM 128
#define OUT_DIM 64
#define HEADS 4
#define HC 256              // HEADS * OUT_DIM
#define NEG_SLOPE 0.2f
#define EPS_DEN 1e-16f

#define M_TILES ((N_SRC + 127) / 128)   // 391

// ---------------- scratch (device globals; no allocation allowed) ----------
// g_hsh layout: [node][c_pair 0..31][head 0..3] as half2 -> 32 uint4 per node.
__device__ __half g_hsh[(size_t)N_SRC * HC];      // 25.6 MB projected src feats (fp16)
__device__ __half g_wt[256 * 128];                // W^T fp16 [n][k] row-major (64KB)
__device__ float g_as[N_SRC * HEADS];             // per-node src logits
__device__ float g_ad[N_DST * HEADS];             // per-node dst logits
__device__ float g_vs[IN_DIM * HEADS];            // W_src @ att_src (folded)
__device__ float g_vd[IN_DIM * HEADS];            // W_dst @ att_dst (folded)
__device__ int   g_deg[N_DST];                    // in-degree (zero at launch entry;
                                                  //  re-zeroed by k_gather each launch)
__device__ int   g_off[N_DST];                    // CSR row offsets
__device__ int   g_cur[N_DST];                    // CSR write cursors
__device__ float4 g_ep_eo[NEDGE];                 // edge-order exp(logits) (12.8 MB)
__device__ uint4  g_rec[NEDGE];                   // CSR records {h2 ep01, h2 ep23, src, pad}

// ---------------- mma/ldmatrix helpers (family-portable, sm_80+) -----------
__device__ __forceinline__ void ldsm_x4(uint32_t& r0, uint32_t& r1, uint32_t& r2,
                                        uint32_t& r3, uint32_t addr) {
    asm volatile("ldmatrix.sync.aligned.m8n8.x4.shared.b16 {%0,%1,%2,%3}, [%4];"
                 : "=r"(r0), "=r"(r1), "=r"(r2), "=r"(r3) : "r"(addr));
}
__device__ __forceinline__ void mma16816(float& d0, float& d1, float& d2, float& d3,
                                         uint32_t a0, uint32_t a1, uint32_t a2, uint32_t a3,
                                         uint32_t b0, uint32_t b1) {
    asm volatile(
        "mma.sync.aligned.m16n8k16.row.col.f32.f16.f16.f32 "
        "{%0,%1,%2,%3}, {%4,%5,%6,%7}, {%8,%9}, {%0,%1,%2,%3};"
        : "+f"(d0), "+f"(d1), "+f"(d2), "+f"(d3)
        : "r"(a0), "r"(a1), "r"(a2), "r"(a3), "r"(b0), "r"(b1));
}

// ---------------- kernels ---------------------------------------------------

// transpose + fp16-convert W_src -> g_wt [n=256][k=128] row-major
__global__ void k_wt(const float* __restrict__ W) {
    int t = blockIdx.x * blockDim.x + threadIdx.x;   // 0..16383 (one half2 each)
    int n = t & 255;
    int k2 = t >> 8;                                 // half2 index 0..63
    float w0 = W[(size_t)(2 * k2) * HC + n];
    float w1 = W[(size_t)(2 * k2 + 1) * HC + n];
    __half2 h = __floats2half2_rn(w0, w1);
    *reinterpret_cast<__half2*>(&g_wt[n * 128 + 2 * k2]) = h;
}

// v_s[k,h] = sum_c W_src[k, h*64+c] * att_src[h,c]   (and same for dst)
__global__ void k_vec(const float* __restrict__ Ws, const float* __restrict__ Wd,
                      const float* __restrict__ att_s, const float* __restrict__ att_d) {
    int t = threadIdx.x;            // 512 threads, 1 block
    int k = t >> 2;
    int h = t & 3;
    float s = 0.0f, d = 0.0f;
#pragma unroll 8
    for (int c = 0; c < OUT_DIM; c++) {
        s += Ws[(size_t)k * HC + h * OUT_DIM + c] * att_s[h * OUT_DIM + c];
        d += Wd[(size_t)k * HC + h * OUT_DIM + c] * att_d[h * OUT_DIM + c];
    }
    g_vs[k * HEADS + h] = s;
    g_vd[k * HEADS + h] = d;
}

// a_s = x_src @ v_s ; a_d = x_dst @ v_d.  4 threads per node, coalesced.
__global__ void k_logits(const float* __restrict__ xs, const float* __restrict__ xd) {
    __shared__ float vs[IN_DIM * HEADS];
    __shared__ float vd[IN_DIM * HEADS];
    for (int i = threadIdx.x; i < IN_DIM * HEADS; i += blockDim.x) {
        vs[i] = g_vs[i];
        vd[i] = g_vd[i];
    }
    __syncthreads();
    int idx = blockIdx.x * blockDim.x + threadIdx.x;
    int n = idx >> 2;
    int g = idx & 3;
    if (n >= N_SRC) return;

    float ss[4] = {0.f, 0.f, 0.f, 0.f};
    float dd[4] = {0.f, 0.f, 0.f, 0.f};
    const float4* xr  = reinterpret_cast<const float4*>(xs + (size_t)n * IN_DIM);
    const float4* xdr = reinterpret_cast<const float4*>(xd + (size_t)n * IN_DIM);
#pragma unroll
    for (int k4 = 0; k4 < 8; k4++) {
        int f4 = k4 * 4 + g;
        float4 a = xr[f4];
        float4 b = xdr[f4];
        int base = f4 * 4 * HEADS;
#pragma unroll
        for (int h = 0; h < HEADS; h++) {
            ss[h] += a.x * vs[base + 0 * HEADS + h] + a.y * vs[base + 1 * HEADS + h]
                   + a.z * vs[base + 2 * HEADS + h] + a.w * vs[base + 3 * HEADS + h];
            dd[h] += b.x * vd[base + 0 * HEADS + h] + b.y * vd[base + 1 * HEADS + h]
                   + b.z * vd[base + 2 * HEADS + h] + b.w * vd[base + 3 * HEADS + h];
        }
    }
#pragma unroll
    for (int off = 1; off < 4; off <<= 1) {
#pragma unroll
        for (int h = 0; h < HEADS; h++) {
            ss[h] += __shfl_xor_sync(0xffffffffu, ss[h], off);
            dd[h] += __shfl_xor_sync(0xffffffffu, dd[h], off);
        }
    }
    if (g == 0) {
        *reinterpret_cast<float4*>(&g_as[n * HEADS]) = make_float4(ss[0], ss[1], ss[2], ss[3]);
        *reinterpret_cast<float4*>(&g_ad[n * HEADS]) = make_float4(dd[0], dd[1], dd[2], dd[3]);
    }
}

// hs = x_src @ W_src via HMMA (fp16 in, f32 accum) -> g_hsh (head-interleaved)
#define AS_STRIDE 272
#define AS_BYTES (128 * AS_STRIDE)       // 34816
#define BS_BYTES (256 * AS_STRIDE)       // 69632
#define SM_TOTAL (AS_BYTES + BS_BYTES)   // 104448

__global__ void __launch_bounds__(512) k_gemm_mma(const float* __restrict__ A) {
    extern __shared__ char smem[];
    char* As = smem;
    char* Bs = smem + AS_BYTES;
    int tid = threadIdx.x;
    int lane = tid & 31;
    int warp = tid >> 5;
    int rowBase = blockIdx.x * 128;

    for (int i = tid; i < 128 * 32; i += 512) {
        int r = i >> 5;
        int c4 = i & 31;
        int grow = rowBase + r;
        float4 v = make_float4(0.f, 0.f, 0.f, 0.f);
        if (grow < N_SRC)
            v = *reinterpret_cast<const float4*>(&A[(size_t)grow * IN_DIM + c4 * 4]);
        __half2 h0 = __floats2half2_rn(v.x, v.y);
        __half2 h1 = __floats2half2_rn(v.z, v.w);
        uint2 st;
        st.x = *reinterpret_cast<uint32_t*>(&h0);
        st.y = *reinterpret_cast<uint32_t*>(&h1);
        *reinterpret_cast<uint2*>(As + r * AS_STRIDE + c4 * 8) = st;
    }
    for (int i = tid; i < 256 * 16; i += 512) {
        int r = i >> 4;
        int c = i & 15;
        uint4 v = *reinterpret_cast<const uint4*>(&g_wt[r * 128 + c * 8]);
        *reinterpret_cast<uint4*>(Bs + r * AS_STRIDE + c * 16) = v;
    }
    __syncthreads();

    int wm = warp >> 2;
    int wn = warp & 3;
    int m0 = wm * 32;
    int n0 = wn * 64;

    float acc[2][8][4];
#pragma unroll
    for (int mi = 0; mi < 2; mi++)
#pragma unroll
        for (int ni = 0; ni < 8; ni++)
#pragma unroll
            for (int q = 0; q < 4; q++) acc[mi][ni][q] = 0.f;

    uint32_t asb = (uint32_t)__cvta_generic_to_shared(As);
    uint32_t bsb = (uint32_t)__cvta_generic_to_shared(Bs);

#pragma unroll
    for (int ks = 0; ks < 8; ks++) {
        int kb = ks * 32;
        uint32_t a[2][4];
#pragma unroll
        for (int mi = 0; mi < 2; mi++) {
            uint32_t addr = asb + (m0 + mi * 16 + (lane & 15)) * AS_STRIDE
                          + kb + (lane >> 4) * 16;
            ldsm_x4(a[mi][0], a[mi][1], a[mi][2], a[mi][3], addr);
        }
        uint32_t b[8][2];
#pragma unroll
        for (int np = 0; np < 4; np++) {
            int q = lane >> 3;
            int row = n0 + np * 16 + (q >> 1) * 8 + (lane & 7);
            uint32_t addr = bsb + row * AS_STRIDE + kb + (q & 1) * 16;
            ldsm_x4(b[np * 2][0], b[np * 2][1], b[np * 2 + 1][0], b[np * 2 + 1][1], addr);
        }
#pragma unroll
        for (int mi = 0; mi < 2; mi++)
#pragma unroll
            for (int ni = 0; ni < 8; ni++)
                mma16816(acc[mi][ni][0], acc[mi][ni][1], acc[mi][ni][2], acc[mi][ni][3],
                         a[mi][0], a[mi][1], a[mi][2], a[mi][3],
                         b[ni][0], b[ni][1]);
    }

    // epilogue -> head-interleaved layout: half off = row*256 + (ch>>1)*8 + h*2
#pragma unroll
    for (int mi = 0; mi < 2; mi++) {
        int r0 = rowBase + m0 + mi * 16 + (lane >> 2);
        int r1 = r0 + 8;
#pragma unroll
        for (int ni = 0; ni < 8; ni++) {
            int col = n0 + ni * 8 + 2 * (lane & 3);
            int h = col >> 6;
            int ch = col & 63;
            size_t off = (size_t)(ch >> 1) * 8 + h * 2;
            if (r0 < N_SRC) {
                __half2 v = __floats2half2_rn(acc[mi][ni][0], acc[mi][ni][1]);
                *reinterpret_cast<__half2*>(&g_hsh[(size_t)r0 * HC + off]) = v;
            }
            if (r1 < N_SRC) {
                __half2 v = __floats2half2_rn(acc[mi][ni][2], acc[mi][ni][3]);
                *reinterpret_cast<__half2*>(&g_hsh[(size_t)r1 * HC + off]) = v;
            }
        }
    }
}

// in-degree histogram (4 edges per thread, vectorized reads)
__global__ void k_hist(const int* __restrict__ dst) {
    int t = blockIdx.x * blockDim.x + threadIdx.x;
    if (t * 4 >= NEDGE) return;
    int4 d4 = *reinterpret_cast<const int4*>(&dst[t * 4]);
    atomicAdd(&g_deg[d4.x], 1);
    atomicAdd(&g_deg[d4.y], 1);
    atomicAdd(&g_deg[d4.z], 1);
    atomicAdd(&g_deg[d4.w], 1);
}

// exclusive scan of g_deg -> g_off, g_cur.  Single block of 1024 threads.
__global__ void __launch_bounds__(1024) k_scan() {
    __shared__ int sums[1024];
    const int CH = (N_DST + 1023) / 1024;   // 49
    int t = threadIdx.x;
    int beg = t * CH;
    int end = beg + CH; if (end > N_DST) end = N_DST;
    int s = 0;
    for (int i = beg; i < end; i++) s += g_deg[i];
    sums[t] = s;
    __syncthreads();
    for (int off = 1; off < 1024; off <<= 1) {
        int v = (t >= off) ? sums[t - off] : 0;
        __syncthreads();
        sums[t] += v;
        __syncthreads();
    }
    int run = (t == 0) ? 0 : sums[t - 1];
    for (int i = beg; i < end; i++) {
        g_off[i] = run;
        g_cur[i] = run;
        run += g_deg[i];
    }
}

__device__ __forceinline__ float lrelu(float v) {
    return v > 0.0f ? v : NEG_SLOPE * v;
}

// per-edge exp(leaky(a_s[src]+a_d[dst])) in EDGE order (runs on aux1,
// overlapped with hist/scan; only depends on logits)
__global__ void k_ep(const int* __restrict__ src, const int* __restrict__ dst) {
    int e = blockIdx.x * blockDim.x + threadIdx.x;
    if (e >= NEDGE) return;
    int s = src[e], d = dst[e];
    float4 as4 = *reinterpret_cast<const float4*>(&g_as[s * HEADS]);
    float4 ad4 = *reinterpret_cast<const float4*>(&g_ad[d * HEADS]);
    float4 pp;
    pp.x = expf(lrelu(as4.x + ad4.x));
    pp.y = expf(lrelu(as4.y + ad4.y));
    pp.z = expf(lrelu(as4.z + ad4.z));
    pp.w = expf(lrelu(as4.w + ad4.w));
    g_ep_eo[e] = pp;
}

// bucket records into CSR order: pack {fp16x4 ep, src} into ONE 16B record.
// 2 edges per thread, int2 coalesced index reads.
__global__ void k_bucket(const int* __restrict__ src, const int* __restrict__ dst) {
    int t = blockIdx.x * blockDim.x + threadIdx.x;
    int e = t * 2;
    if (e >= NEDGE) return;
    int2 d2 = *reinterpret_cast<const int2*>(&dst[e]);
    int2 s2 = *reinterpret_cast<const int2*>(&src[e]);
    float4 p0 = g_ep_eo[e];
    float4 p1 = g_ep_eo[e + 1];

    __half2 a01 = __floats2half2_rn(p0.x, p0.y);
    __half2 a23 = __floats2half2_rn(p0.z, p0.w);
    uint4 r0;
    r0.x = *reinterpret_cast<uint32_t*>(&a01);
    r0.y = *reinterpret_cast<uint32_t*>(&a23);
    r0.z = (uint32_t)s2.x;
    r0.w = 0;
    __half2 b01 = __floats2half2_rn(p1.x, p1.y);
    __half2 b23 = __floats2half2_rn(p1.z, p1.w);
    uint4 r1;
    r1.x = *reinterpret_cast<uint32_t*>(&b01);
    r1.y = *reinterpret_cast<uint32_t*>(&b23);
    r1.z = (uint32_t)s2.y;
    r1.w = 0;

    int pos0 = atomicAdd(&g_cur[d2.x], 1);
    g_rec[pos0] = r0;
    int pos1 = atomicAdd(&g_cur[d2.y], 1);
    g_rec[pos1] = r1;
}

// gather: 1 warp per dst node; lane c2 owns channels (2c2, 2c2+1) of all heads.
// ONE 16B record load per edge (ep fp16x4 + src packed). R9 loop shape.
__global__ void __launch_bounds__(256) k_gather(const float* __restrict__ bias,
                                                float* __restrict__ out) {
    int node = blockIdx.x * 8 + (threadIdx.x >> 5);
    int c2 = threadIdx.x & 31;
    if (node >= N_DST) return;
    int beg = g_off[node];
    int n = g_deg[node];
    int end = beg + n;

    const uint4* hsv = reinterpret_cast<const uint4*>(g_hsh);   // 32 uint4 / node

    float a0x = 0.f, a0y = 0.f, a1x = 0.f, a1y = 0.f;
    float a2x = 0.f, a2y = 0.f, a3x = 0.f, a3y = 0.f;
    float d0 = 0.f, d1 = 0.f, d2 = 0.f, d3 = 0.f;

#define ACC_EDGE(r, v) do { \
        float2 pa = __half22float2(*reinterpret_cast<const __half2*>(&(r).x)); \
        float2 pb = __half22float2(*reinterpret_cast<const __half2*>(&(r).y)); \
        float2 f0 = __half22float2(*reinterpret_cast<const __half2*>(&(v).x)); \
        float2 f1 = __half22float2(*reinterpret_cast<const __half2*>(&(v).y)); \
        float2 f2 = __half22float2(*reinterpret_cast<const __half2*>(&(v).z)); \
        float2 f3 = __half22float2(*reinterpret_cast<const __half2*>(&(v).w)); \
        d0 += pa.x; d1 += pa.y; d2 += pb.x; d3 += pb.y; \
        a0x += pa.x * f0.x; a0y += pa.x * f0.y; \
        a1x += pa.y * f1.x; a1y += pa.y * f1.y; \
        a2x += pb.x * f2.x; a2y += pb.x * f2.y; \
        a3x += pb.y * f3.x; a3y += pb.y * f3.y; \
    } while (0)

    int i = beg;
    for (; i + 4 <= end; i += 4) {
        uint4 r0 = g_rec[i + 0];
        uint4 r1 = g_rec[i + 1];
        uint4 r2 = g_rec[i + 2];
        uint4 r3 = g_rec[i + 3];
        uint4 v0 = hsv[(size_t)r0.z * 32 + c2];
        uint4 v1 = hsv[(size_t)r1.z * 32 + c2];
        uint4 v2 = hsv[(size_t)r2.z * 32 + c2];
        uint4 v3 = hsv[(size_t)r3.z * 32 + c2];
        ACC_EDGE(r0, v0);
        ACC_EDGE(r1, v1);
        ACC_EDGE(r2, v2);
        ACC_EDGE(r3, v3);
    }
    for (; i < end; i++) {
        uint4 r = g_rec[i];
        uint4 v = hsv[(size_t)r.z * 32 + c2];
        ACC_EDGE(r, v);
    }
#undef ACC_EDGE

    float r0 = 0.25f / (d0 + EPS_DEN);
    float r1 = 0.25f / (d1 + EPS_DEN);
    float r2 = 0.25f / (d2 + EPS_DEN);
    float r3 = 0.25f / (d3 + EPS_DEN);

    float2 res;
    res.x = a0x * r0 + a1x * r1 + a2x * r2 + a3x * r3 + bias[c2 * 2];
    res.y = a0y * r0 + a1y * r1 + a2y * r2 + a3y * r3 + bias[c2 * 2 + 1];
    *reinterpret_cast<float2*>(&out[(size_t)node * OUT_DIM + c2 * 2]) = res;

    if (c2 == 0) g_deg[node] = 0;   // clean histogram for next launch
}

// ---------------- streams / events (created at load, reused) ----------------
static cudaStream_t s_aux1, s_aux2;
static cudaEvent_t ev_root, ev_ep, ev_gemm;
static int s_init = [] {
    cudaStreamCreateWithFlags(&s_aux1, cudaStreamNonBlocking);
    cudaStreamCreateWithFlags(&s_aux2, cudaStreamNonBlocking);
    cudaEventCreateWithFlags(&ev_root, cudaEventDisableTiming);
    cudaEventCreateWithFlags(&ev_ep, cudaEventDisableTiming);
    cudaEventCreateWithFlags(&ev_gemm, cudaEventDisableTiming);
    return 0;
}();

// ---------------- launch ----------------------------------------------------

extern "C" void kernel_launch(void* const* d_in, const int* in_sizes, int n_in,
                              void* d_out, int out_size) {
    const float* x_src   = (const float*)d_in[0];
    const float* x_dst   = (const float*)d_in[1];
    const int*   ei      = (const int*)d_in[2];   // [2, E] : src row then dst row
    const float* W_src   = (const float*)d_in[3];
    const float* W_dst   = (const float*)d_in[4];
    const float* att_src = (const float*)d_in[5];
    const float* att_dst = (const float*)d_in[6];
    const float* bias    = (const float*)d_in[7];
    float* out = (float*)d_out;

    const int* src = ei;
    const int* dst = ei + NEDGE;

    cudaFuncSetAttribute(k_gemm_mma, cudaFuncAttributeMaxDynamicSharedMemorySize, SM_TOTAL);

    cudaStream_t s0 = 0;   // capture-origin (default) stream

    // fork
    cudaEventRecord(ev_root, s0);
    cudaStreamWaitEvent(s_aux1, ev_root, 0);
    cudaStreamWaitEvent(s_aux2, ev_root, 0);

    // aux1: logits chain + edge-order ep (off the critical path)
    k_vec<<<1, 512, 0, s_aux1>>>(W_src, W_dst, att_src, att_dst);
    k_logits<<<(N_SRC * 4 + 255) / 256, 256, 0, s_aux1>>>(x_src, x_dst);
    k_ep<<<(NEDGE + 255) / 256, 256, 0, s_aux1>>>(src, dst);
    cudaEventRecord(ev_ep, s_aux1);

    // aux2: gemm chain
    k_wt<<<64, 256, 0, s_aux2>>>(W_src);
    k_gemm_mma<<<M_TILES, 512, SM_TOTAL, s_aux2>>>(x_src);
    cudaEventRecord(ev_gemm, s_aux2);

    // origin: hist chain, then joins (g_deg is zero at entry: zero-initialized
    // at load; k_gather re-zeroes it at the end of every launch)
    k_hist<<<(NEDGE / 4 + 255) / 256, 256, 0, s0>>>(dst);
    k_scan<<<1, 1024, 0, s0>>>();
    cudaStreamWaitEvent(s0, ev_ep, 0);
    k_bucket<<<(NEDGE / 2 + 255) / 256, 256, 0, s0>>>(src, dst);
    cudaStreamWaitEvent(s0, ev_gemm, 0);
    k_gather<<<(N_DST + 7) / 8, 256, 0, s0>>>(bias, out);
}

// round 17
// speedup vs baseline: 1.0340x; 1.0340x over previous
#include <cuda_runtime.h>
#include <cuda_fp16.h>
#include <cstdint>

#define N_SRC 50000
#define N_DST 50000
#define NEDGE 800000
#define IN_DIM 128
#define OUT_DIM 64
#define HEADS 4
#define HC 256              // HEADS * OUT_DIM
#define NEG_SLOPE 0.2f
#define EPS_DEN 1e-16f

#define M_TILES ((N_SRC + 127) / 128)   // 391

// ---------------- scratch (device globals; no allocation allowed) ----------
// g_hsh layout: [node][c_pair 0..31][head 0..3] as half2 -> 32 uint4 per node.
__device__ __half g_hsh[(size_t)N_SRC * HC];      // 25.6 MB projected src feats (fp16)
__device__ __half g_wt[256 * 128];                // W^T fp16 [n][k] row-major (64KB)
__device__ float g_as[N_SRC * HEADS];             // per-node src logits
__device__ float g_ad[N_DST * HEADS];             // per-node dst logits
__device__ float g_vs[IN_DIM * HEADS];            // W_src @ att_src (folded)
__device__ float g_vd[IN_DIM * HEADS];            // W_dst @ att_dst (folded)
__device__ int   g_deg[N_DST];                    // in-degree (zero at launch entry;
                                                  //  re-zeroed by k_gather each launch)
__device__ int   g_off[N_DST];                    // CSR row offsets
__device__ int   g_cur[N_DST];                    // CSR write cursors
__device__ float4 g_ep_eo[NEDGE];                 // edge-order exp(logits) (12.8 MB)
__device__ uint4  g_rec[NEDGE];                   // CSR records {h2 ep01, h2 ep23, src, pad}

// ---------------- mma/ldmatrix helpers (family-portable, sm_80+) -----------
__device__ __forceinline__ void ldsm_x4(uint32_t& r0, uint32_t& r1, uint32_t& r2,
                                        uint32_t& r3, uint32_t addr) {
    asm volatile("ldmatrix.sync.aligned.m8n8.x4.shared.b16 {%0,%1,%2,%3}, [%4];"
                 : "=r"(r0), "=r"(r1), "=r"(r2), "=r"(r3) : "r"(addr));
}
__device__ __forceinline__ void mma16816(float& d0, float& d1, float& d2, float& d3,
                                         uint32_t a0, uint32_t a1, uint32_t a2, uint32_t a3,
                                         uint32_t b0, uint32_t b1) {
    asm volatile(
        "mma.sync.aligned.m16n8k16.row.col.f32.f16.f16.f32 "
        "{%0,%1,%2,%3}, {%4,%5,%6,%7}, {%8,%9}, {%0,%1,%2,%3};"
        : "+f"(d0), "+f"(d1), "+f"(d2), "+f"(d3)
        : "r"(a0), "r"(a1), "r"(a2), "r"(a3), "r"(b0), "r"(b1));
}

// ---------------- kernels ---------------------------------------------------

// transpose + fp16-convert W_src -> g_wt [n=256][k=128] row-major
__global__ void k_wt(const float* __restrict__ W) {
    int t = blockIdx.x * blockDim.x + threadIdx.x;   // 0..16383 (one half2 each)
    int n = t & 255;
    int k2 = t >> 8;                                 // half2 index 0..63
    float w0 = W[(size_t)(2 * k2) * HC + n];
    float w1 = W[(size_t)(2 * k2 + 1) * HC + n];
    __half2 h = __floats2half2_rn(w0, w1);
    *reinterpret_cast<__half2*>(&g_wt[n * 128 + 2 * k2]) = h;
}

// v_s[k,h] = sum_c W_src[k, h*64+c] * att_src[h,c]   (and same for dst)
__global__ void k_vec(const float* __restrict__ Ws, const float* __restrict__ Wd,
                      const float* __restrict__ att_s, const float* __restrict__ att_d) {
    int t = threadIdx.x;            // 512 threads, 1 block
    int k = t >> 2;
    int h = t & 3;
    float s = 0.0f, d = 0.0f;
#pragma unroll 8
    for (int c = 0; c < OUT_DIM; c++) {
        s += Ws[(size_t)k * HC + h * OUT_DIM + c] * att_s[h * OUT_DIM + c];
        d += Wd[(size_t)k * HC + h * OUT_DIM + c] * att_d[h * OUT_DIM + c];
    }
    g_vs[k * HEADS + h] = s;
    g_vd[k * HEADS + h] = d;
}

// a_s = x_src @ v_s ; a_d = x_dst @ v_d.  4 threads per node, coalesced.
__global__ void k_logits(const float* __restrict__ xs, const float* __restrict__ xd) {
    __shared__ float vs[IN_DIM * HEADS];
    __shared__ float vd[IN_DIM * HEADS];
    for (int i = threadIdx.x; i < IN_DIM * HEADS; i += blockDim.x) {
        vs[i] = g_vs[i];
        vd[i] = g_vd[i];
    }
    __syncthreads();
    int idx = blockIdx.x * blockDim.x + threadIdx.x;
    int n = idx >> 2;
    int g = idx & 3;
    if (n >= N_SRC) return;

    float ss[4] = {0.f, 0.f, 0.f, 0.f};
    float dd[4] = {0.f, 0.f, 0.f, 0.f};
    const float4* xr  = reinterpret_cast<const float4*>(xs + (size_t)n * IN_DIM);
    const float4* xdr = reinterpret_cast<const float4*>(xd + (size_t)n * IN_DIM);
#pragma unroll
    for (int k4 = 0; k4 < 8; k4++) {
        int f4 = k4 * 4 + g;
        float4 a = xr[f4];
        float4 b = xdr[f4];
        int base = f4 * 4 * HEADS;
#pragma unroll
        for (int h = 0; h < HEADS; h++) {
            ss[h] += a.x * vs[base + 0 * HEADS + h] + a.y * vs[base + 1 * HEADS + h]
                   + a.z * vs[base + 2 * HEADS + h] + a.w * vs[base + 3 * HEADS + h];
            dd[h] += b.x * vd[base + 0 * HEADS + h] + b.y * vd[base + 1 * HEADS + h]
                   + b.z * vd[base + 2 * HEADS + h] + b.w * vd[base + 3 * HEADS + h];
        }
    }
#pragma unroll
    for (int off = 1; off < 4; off <<= 1) {
#pragma unroll
        for (int h = 0; h < HEADS; h++) {
            ss[h] += __shfl_xor_sync(0xffffffffu, ss[h], off);
            dd[h] += __shfl_xor_sync(0xffffffffu, dd[h], off);
        }
    }
    if (g == 0) {
        *reinterpret_cast<float4*>(&g_as[n * HEADS]) = make_float4(ss[0], ss[1], ss[2], ss[3]);
        *reinterpret_cast<float4*>(&g_ad[n * HEADS]) = make_float4(dd[0], dd[1], dd[2], dd[3]);
    }
}

// hs = x_src @ W_src via HMMA (fp16 in, f32 accum) -> g_hsh (head-interleaved)
#define AS_STRIDE 272
#define AS_BYTES (128 * AS_STRIDE)       // 34816
#define BS_BYTES (256 * AS_STRIDE)       // 69632
#define SM_TOTAL (AS_BYTES + BS_BYTES)   // 104448

__global__ void __launch_bounds__(512) k_gemm_mma(const float* __restrict__ A) {
    extern __shared__ char smem[];
    char* As = smem;
    char* Bs = smem + AS_BYTES;
    int tid = threadIdx.x;
    int lane = tid & 31;
    int warp = tid >> 5;
    int rowBase = blockIdx.x * 128;

    for (int i = tid; i < 128 * 32; i += 512) {
        int r = i >> 5;
        int c4 = i & 31;
        int grow = rowBase + r;
        float4 v = make_float4(0.f, 0.f, 0.f, 0.f);
        if (grow < N_SRC)
            v = *reinterpret_cast<const float4*>(&A[(size_t)grow * IN_DIM + c4 * 4]);
        __half2 h0 = __floats2half2_rn(v.x, v.y);
        __half2 h1 = __floats2half2_rn(v.z, v.w);
        uint2 st;
        st.x = *reinterpret_cast<uint32_t*>(&h0);
        st.y = *reinterpret_cast<uint32_t*>(&h1);
        *reinterpret_cast<uint2*>(As + r * AS_STRIDE + c4 * 8) = st;
    }
    for (int i = tid; i < 256 * 16; i += 512) {
        int r = i >> 4;
        int c = i & 15;
        uint4 v = *reinterpret_cast<const uint4*>(&g_wt[r * 128 + c * 8]);
        *reinterpret_cast<uint4*>(Bs + r * AS_STRIDE + c * 16) = v;
    }
    __syncthreads();

    int wm = warp >> 2;
    int wn = warp & 3;
    int m0 = wm * 32;
    int n0 = wn * 64;

    float acc[2][8][4];
#pragma unroll
    for (int mi = 0; mi < 2; mi++)
#pragma unroll
        for (int ni = 0; ni < 8; ni++)
#pragma unroll
            for (int q = 0; q < 4; q++) acc[mi][ni][q] = 0.f;

    uint32_t asb = (uint32_t)__cvta_generic_to_shared(As);
    uint32_t bsb = (uint32_t)__cvta_generic_to_shared(Bs);

#pragma unroll
    for (int ks = 0; ks < 8; ks++) {
        int kb = ks * 32;
        uint32_t a[2][4];
#pragma unroll
        for (int mi = 0; mi < 2; mi++) {
            uint32_t addr = asb + (m0 + mi * 16 + (lane & 15)) * AS_STRIDE
                          + kb + (lane >> 4) * 16;
            ldsm_x4(a[mi][0], a[mi][1], a[mi][2], a[mi][3], addr);
        }
        uint32_t b[8][2];
#pragma unroll
        for (int np = 0; np < 4; np++) {
            int q = lane >> 3;
            int row = n0 + np * 16 + (q >> 1) * 8 + (lane & 7);
            uint32_t addr = bsb + row * AS_STRIDE + kb + (q & 1) * 16;
            ldsm_x4(b[np * 2][0], b[np * 2][1], b[np * 2 + 1][0], b[np * 2 + 1][1], addr);
        }
#pragma unroll
        for (int mi = 0; mi < 2; mi++)
#pragma unroll
            for (int ni = 0; ni < 8; ni++)
                mma16816(acc[mi][ni][0], acc[mi][ni][1], acc[mi][ni][2], acc[mi][ni][3],
                         a[mi][0], a[mi][1], a[mi][2], a[mi][3],
                         b[ni][0], b[ni][1]);
    }

    // epilogue -> head-interleaved layout: half off = row*256 + (ch>>1)*8 + h*2
#pragma unroll
    for (int mi = 0; mi < 2; mi++) {
        int r0 = rowBase + m0 + mi * 16 + (lane >> 2);
        int r1 = r0 + 8;
#pragma unroll
        for (int ni = 0; ni < 8; ni++) {
            int col = n0 + ni * 8 + 2 * (lane & 3);
            int h = col >> 6;
            int ch = col & 63;
            size_t off = (size_t)(ch >> 1) * 8 + h * 2;
            if (r0 < N_SRC) {
                __half2 v = __floats2half2_rn(acc[mi][ni][0], acc[mi][ni][1]);
                *reinterpret_cast<__half2*>(&g_hsh[(size_t)r0 * HC + off]) = v;
            }
            if (r1 < N_SRC) {
                __half2 v = __floats2half2_rn(acc[mi][ni][2], acc[mi][ni][3]);
                *reinterpret_cast<__half2*>(&g_hsh[(size_t)r1 * HC + off]) = v;
            }
        }
    }
}

// in-degree histogram (4 edges per thread, vectorized reads)
__global__ void k_hist(const int* __restrict__ dst) {
    int t = blockIdx.x * blockDim.x + threadIdx.x;
    if (t * 4 >= NEDGE) return;
    int4 d4 = *reinterpret_cast<const int4*>(&dst[t * 4]);
    atomicAdd(&g_deg[d4.x], 1);
    atomicAdd(&g_deg[d4.y], 1);
    atomicAdd(&g_deg[d4.z], 1);
    atomicAdd(&g_deg[d4.w], 1);
}

// exclusive scan of g_deg -> g_off, g_cur.  Single block of 1024 threads.
__global__ void __launch_bounds__(1024) k_scan() {
    __shared__ int sums[1024];
    const int CH = (N_DST + 1023) / 1024;   // 49
    int t = threadIdx.x;
    int beg = t * CH;
    int end = beg + CH; if (end > N_DST) end = N_DST;
    int s = 0;
    for (int i = beg; i < end; i++) s += g_deg[i];
    sums[t] = s;
    __syncthreads();
    for (int off = 1; off < 1024; off <<= 1) {
        int v = (t >= off) ? sums[t - off] : 0;
        __syncthreads();
        sums[t] += v;
        __syncthreads();
    }
    int run = (t == 0) ? 0 : sums[t - 1];
    for (int i = beg; i < end; i++) {
        g_off[i] = run;
        g_cur[i] = run;
        run += g_deg[i];
    }
}

__device__ __forceinline__ float lrelu(float v) {
    return v > 0.0f ? v : NEG_SLOPE * v;
}

// per-edge exp(leaky(a_s[src]+a_d[dst])) in EDGE order (runs on aux1,
// overlapped with hist/scan; only depends on logits)
__global__ void k_ep(const int* __restrict__ src, const int* __restrict__ dst) {
    int e = blockIdx.x * blockDim.x + threadIdx.x;
    if (e >= NEDGE) return;
    int s = src[e], d = dst[e];
    float4 as4 = *reinterpret_cast<const float4*>(&g_as[s * HEADS]);
    float4 ad4 = *reinterpret_cast<const float4*>(&g_ad[d * HEADS]);
    float4 pp;
    pp.x = expf(lrelu(as4.x + ad4.x));
    pp.y = expf(lrelu(as4.y + ad4.y));
    pp.z = expf(lrelu(as4.z + ad4.z));
    pp.w = expf(lrelu(as4.w + ad4.w));
    g_ep_eo[e] = pp;
}

// bucket records into CSR order: pack {fp16x4 ep, src} into ONE 16B record.
// 2 edges per thread, int2 coalesced index reads.
__global__ void k_bucket(const int* __restrict__ src, const int* __restrict__ dst) {
    int t = blockIdx.x * blockDim.x + threadIdx.x;
    int e = t * 2;
    if (e >= NEDGE) return;
    int2 d2 = *reinterpret_cast<const int2*>(&dst[e]);
    int2 s2 = *reinterpret_cast<const int2*>(&src[e]);
    float4 p0 = g_ep_eo[e];
    float4 p1 = g_ep_eo[e + 1];

    __half2 a01 = __floats2half2_rn(p0.x, p0.y);
    __half2 a23 = __floats2half2_rn(p0.z, p0.w);
    uint4 r0;
    r0.x = *reinterpret_cast<uint32_t*>(&a01);
    r0.y = *reinterpret_cast<uint32_t*>(&a23);
    r0.z = (uint32_t)s2.x;
    r0.w = 0;
    __half2 b01 = __floats2half2_rn(p1.x, p1.y);
    __half2 b23 = __floats2half2_rn(p1.z, p1.w);
    uint4 r1;
    r1.x = *reinterpret_cast<uint32_t*>(&b01);
    r1.y = *reinterpret_cast<uint32_t*>(&b23);
    r1.z = (uint32_t)s2.y;
    r1.w = 0;

    int pos0 = atomicAdd(&g_cur[d2.x], 1);
    g_rec[pos0] = r0;
    int pos1 = atomicAdd(&g_cur[d2.y], 1);
    g_rec[pos1] = r1;
}

// gather: 1 warp per dst node; lane c2 owns channels (2c2, 2c2+1) of all heads.
// Records staged through shared memory: one coalesced LDG.128 round per
// 32-edge chunk, then broadcast LDS in the accumulate loop (record latency
// off the dependent chain).
__global__ void __launch_bounds__(256) k_gather(const float* __restrict__ bias,
                                                float* __restrict__ out) {
    __shared__ uint4 srec[8][32];
    int warp = threadIdx.x >> 5;
    int node = blockIdx.x * 8 + warp;
    int c2 = threadIdx.x & 31;
    if (node >= N_DST) return;
    int beg = g_off[node];
    int n = g_deg[node];
    int end = beg + n;

    const uint4* hsv = reinterpret_cast<const uint4*>(g_hsh);   // 32 uint4 / node

    float a0x = 0.f, a0y = 0.f, a1x = 0.f, a1y = 0.f;
    float a2x = 0.f, a2y = 0.f, a3x = 0.f, a3y = 0.f;
    float d0 = 0.f, d1 = 0.f, d2 = 0.f, d3 = 0.f;

#define ACC_EDGE(r, v) do { \
        float2 pa = __half22float2(*reinterpret_cast<const __half2*>(&(r).x)); \
        float2 pb = __half22float2(*reinterpret_cast<const __half2*>(&(r).y)); \
        float2 f0 = __half22float2(*reinterpret_cast<const __half2*>(&(v).x)); \
        float2 f1 = __half22float2(*reinterpret_cast<const __half2*>(&(v).y)); \
        float2 f2 = __half22float2(*reinterpret_cast<const __half2*>(&(v).z)); \
        float2 f3 = __half22float2(*reinterpret_cast<const __half2*>(&(v).w)); \
        d0 += pa.x; d1 += pa.y; d2 += pb.x; d3 += pb.y; \
        a0x += pa.x * f0.x; a0y += pa.x * f0.y; \
        a1x += pa.y * f1.x; a1y += pa.y * f1.y; \
        a2x += pb.x * f2.x; a2y += pb.x * f2.y; \
        a3x += pb.y * f3.x; a3y += pb.y * f3.y; \
    } while (0)

    for (int chunk = beg; chunk < end; chunk += 32) {
        int m = end - chunk; if (m > 32) m = 32;
        if (chunk + c2 < end) srec[warp][c2] = g_rec[chunk + c2];
        __syncwarp();
        int j = 0;
        for (; j + 4 <= m; j += 4) {
            uint4 r0 = srec[warp][j + 0];
            uint4 r1 = srec[warp][j + 1];
            uint4 r2 = srec[warp][j + 2];
            uint4 r3 = srec[warp][j + 3];
            uint4 v0 = hsv[(size_t)r0.z * 32 + c2];
            uint4 v1 = hsv[(size_t)r1.z * 32 + c2];
            uint4 v2 = hsv[(size_t)r2.z * 32 + c2];
            uint4 v3 = hsv[(size_t)r3.z * 32 + c2];
            ACC_EDGE(r0, v0);
            ACC_EDGE(r1, v1);
            ACC_EDGE(r2, v2);
            ACC_EDGE(r3, v3);
        }
        for (; j < m; j++) {
            uint4 r = srec[warp][j];
            uint4 v = hsv[(size_t)r.z * 32 + c2];
            ACC_EDGE(r, v);
        }
        __syncwarp();
    }
#undef ACC_EDGE

    float r0 = 0.25f / (d0 + EPS_DEN);
    float r1 = 0.25f / (d1 + EPS_DEN);
    float r2 = 0.25f / (d2 + EPS_DEN);
    float r3 = 0.25f / (d3 + EPS_DEN);

    float2 res;
    res.x = a0x * r0 + a1x * r1 + a2x * r2 + a3x * r3 + bias[c2 * 2];
    res.y = a0y * r0 + a1y * r1 + a2y * r2 + a3y * r3 + bias[c2 * 2 + 1];
    *reinterpret_cast<float2*>(&out[(size_t)node * OUT_DIM + c2 * 2]) = res;

    if (c2 == 0) g_deg[node] = 0;   // clean histogram for next launch
}

// ---------------- streams / events (created at load, reused) ----------------
static cudaStream_t s_aux1, s_aux2;
static cudaEvent_t ev_root, ev_ep, ev_gemm;
static int s_init = [] {
    cudaStreamCreateWithFlags(&s_aux1, cudaStreamNonBlocking);
    cudaStreamCreateWithFlags(&s_aux2, cudaStreamNonBlocking);
    cudaEventCreateWithFlags(&ev_root, cudaEventDisableTiming);
    cudaEventCreateWithFlags(&ev_ep, cudaEventDisableTiming);
    cudaEventCreateWithFlags(&ev_gemm, cudaEventDisableTiming);
    return 0;
}();

// ---------------- launch ----------------------------------------------------

extern "C" void kernel_launch(void* const* d_in, const int* in_sizes, int n_in,
                              void* d_out, int out_size) {
    const float* x_src   = (const float*)d_in[0];
    const float* x_dst   = (const float*)d_in[1];
    const int*   ei      = (const int*)d_in[2];   // [2, E] : src row then dst row
    const float* W_src   = (const float*)d_in[3];
    const float* W_dst   = (const float*)d_in[4];
    const float* att_src = (const float*)d_in[5];
    const float* att_dst = (const float*)d_in[6];
    const float* bias    = (const float*)d_in[7];
    float* out = (float*)d_out;

    const int* src = ei;
    const int* dst = ei + NEDGE;

    cudaFuncSetAttribute(k_gemm_mma, cudaFuncAttributeMaxDynamicSharedMemorySize, SM_TOTAL);

    cudaStream_t s0 = 0;   // capture-origin (default) stream

    // fork
    cudaEventRecord(ev_root, s0);
    cudaStreamWaitEvent(s_aux1, ev_root, 0);
    cudaStreamWaitEvent(s_aux2, ev_root, 0);

    // aux1: logits chain + edge-order ep (off the critical path)
    k_vec<<<1, 512, 0, s_aux1>>>(W_src, W_dst, att_src, att_dst);
    k_logits<<<(N_SRC * 4 + 255) / 256, 256, 0, s_aux1>>>(x_src, x_dst);
    k_ep<<<(NEDGE + 255) / 256, 256, 0, s_aux1>>>(src, dst);
    cudaEventRecord(ev_ep, s_aux1);

    // aux2: gemm chain
    k_wt<<<64, 256, 0, s_aux2>>>(W_src);
    k_gemm_mma<<<M_TILES, 512, SM_TOTAL, s_aux2>>>(x_src);
    cudaEventRecord(ev_gemm, s_aux2);

    // origin: hist chain, then joins (g_deg is zero at entry: zero-initialized
    // at load; k_gather re-zeroes it at the end of every launch)
    k_hist<<<(NEDGE / 4 + 255) / 256, 256, 0, s0>>>(dst);
    k_scan<<<1, 1024, 0, s0>>>();
    cudaStreamWaitEvent(s0, ev_ep, 0);
    k_bucket<<<(NEDGE / 2 + 255) / 256, 256, 0, s0>>>(src, dst);
    cudaStreamWaitEvent(s0, ev_gemm, 0);
    k_gather<<<(N_DST + 7) / 8, 256, 0, s0>>>(bias, out);
}